// round 16
// baseline (speedup 1.0000x reference)
#include <cuda_runtime.h>
#include <cuda_bf16.h>
#include <cstdint>

// ================= problem constants =================
#define IMG 256
#define BATCH 4
#define HW 65536
#define NPIX 262144          // BATCH*HW

// ================= device scratch (no allocs) =================
// NHWC fp32 planes: 0=fea1 1=bufA 2=bufB 3=bufT
__device__ __align__(16) float g_nhwc[4][(size_t)NPIX * 64];
__device__ float g_core[(size_t)BATCH * 75 * HW];
__device__ float g_res [(size_t)BATCH * 3  * HW];
// fragment-ordered bf16 weights (u32 elements)
#define WF_TRUNK(j) ((size_t)(j) * 36864)
#define WF_C3W2  1179648
#define WF_C3W3  1216512
#define WF_C2W1  1253376
#define WF_C1    1327104
#define WF_C2W2  1419264
#define WF_TOTAL 1423872
__device__ __align__(16) unsigned g_wfrag[WF_TOTAL];

// ================= helpers =================
__device__ __forceinline__ unsigned smem_u32(const void* p) {
    unsigned a;
    asm("{ .reg .u64 t; cvta.to.shared.u64 t, %1; cvt.u32.u64 %0, t; }" : "=r"(a) : "l"(p));
    return a;
}
__device__ __forceinline__ unsigned pk(__nv_bfloat16 a, __nv_bfloat16 b) {
    return (unsigned)__bfloat16_as_ushort(a) | ((unsigned)__bfloat16_as_ushort(b) << 16);
}
#define MMA_BF16(acc, a, b0, b1)                                              \
    asm volatile(                                                             \
        "mma.sync.aligned.m16n8k16.row.col.f32.bf16.bf16.f32 "               \
        "{%0,%1,%2,%3}, {%4,%5,%6,%7}, {%8,%9}, {%0,%1,%2,%3};"              \
        : "+f"((acc)[0]), "+f"((acc)[1]), "+f"((acc)[2]), "+f"((acc)[3])      \
        : "r"((a)[0]), "r"((a)[1]), "r"((a)[2]), "r"((a)[3]),                 \
          "r"(b0), "r"(b1))
#define LDMX4(dst, addr)                                                      \
    asm volatile("ldmatrix.sync.aligned.m8n8.x4.shared.b16 {%0,%1,%2,%3}, [%4];" \
                 : "=r"((dst)[0]), "=r"((dst)[1]), "=r"((dst)[2]), "=r"((dst)[3]) \
                 : "r"(addr))

// ================= merged weight prep: all layers in ONE launch =================
__device__ __forceinline__ void prep_one(const float* __restrict__ w, unsigned* __restrict__ dst,
                                         int idx, int Cout, int CinW, int NT)
{
    int lane2 = idx & 63;
    int lane = lane2 >> 1, r = lane2 & 1;
    int tmp = idx >> 6;
    int ntile = tmp % NT; tmp /= NT;
    int kstep = tmp & 3; tmp >>= 2;
    int term = tmp & 1;
    int chunk = tmp >> 1;
    int src = chunk / 9, t9 = chunk % 9, ky = t9 / 3, kx = t9 % 3;
    int n = ntile * 8 + (lane >> 2);
    int k = kstep * 16 + ((lane & 3) << 1) + 8 * r;
    int ci = src * 64 + k;
    float v0 = 0.f, v1 = 0.f;
    if (n < Cout) {
        if (ci < CinW)     v0 = w[(((size_t)n * CinW + ci) * 3 + ky) * 3 + kx];
        if (ci + 1 < CinW) v1 = w[(((size_t)n * CinW + ci + 1) * 3 + ky) * 3 + kx];
    }
    __nv_bfloat16 h0 = __float2bfloat16(v0), h1 = __float2bfloat16(v1);
    unsigned outv;
    if (term == 0) outv = pk(h0, h1);
    else outv = pk(__float2bfloat16(v0 - __bfloat162float(h0)),
                   __float2bfloat16(v1 - __bfloat162float(h1)));
    dst[idx] = outv;
}

__global__ void prep_all(const float* __restrict__ w_trunk,
                         const float* __restrict__ c3_w2, const float* __restrict__ c3_w3,
                         const float* __restrict__ c2_w1, const float* __restrict__ c1_w,
                         const float* __restrict__ c2_w2, unsigned* __restrict__ wf)
{
    int g = blockIdx.x * 256 + threadIdx.x;
    if (g >= WF_TOTAL) return;
    if (g < WF_C3W2) {
        int j = g / 36864;
        prep_one(w_trunk + (size_t)j * 36864, wf + WF_TRUNK(j), g % 36864, 64, 64, 8);
    } else if (g < WF_C3W3) {
        prep_one(c3_w2, wf + WF_C3W2, g - WF_C3W2, 64, 64, 8);
    } else if (g < WF_C2W1) {
        prep_one(c3_w3, wf + WF_C3W3, g - WF_C3W3, 64, 64, 8);
    } else if (g < WF_C1) {
        prep_one(c2_w1, wf + WF_C2W1, g - WF_C2W1, 64, 128, 8);
    } else if (g < WF_C2W2) {
        prep_one(c1_w, wf + WF_C1, g - WF_C1, 75, 128, 10);
    } else {
        prep_one(c2_w2, wf + WF_C2W2, g - WF_C2W2, 3, 64, 1);
    }
}

// ======== 2-row tensor-core implicit-GEMM 3x3 conv (mma.sync bf16, 3-term) ========
// CTA: 512 threads, 16 warps = 4 M x 4 N. 2 output rows x 128 pixels x 64 couts.
// Per warp: 2 m-tiles x 2 n-tiles x 2 rows (acc = 32 regs). A fragments staged
// (Ah used then overwritten by Al) to fit 64 regs -> 2 CTAs x 16 warps = 32 warps/SM.
__global__ __launch_bounds__(512, 2)
void tc_conv2(const float* __restrict__ a0, const float* __restrict__ a1,
              const unsigned* __restrict__ wf, const float* __restrict__ bias,
              float* __restrict__ outN,
              const float* __restrict__ r0, const float* __restrict__ r1, int relu)
{
    constexpr int HNT = 2;
    __shared__ __nv_bfloat16 sA[2][130][72];   // [hi/lo][slot][ci] stride 144B
    const int tid = threadIdx.x;
    const int lane = tid & 31, wid = tid >> 5;   // 0..15
    const int mw = wid & 3, nw = wid >> 2;       // 4 M x 4 N
    const int t = blockIdx.x;
    const int b = t >> 8, rem = t & 255;
    const int y0 = (rem >> 1) << 1, x0 = (rem & 1) << 7;
    const int nSrc = (a1 != nullptr) ? 2 : 1;
    const unsigned* wfL = wf + (size_t)(nw * HNT) * 64 + lane * 2;

    float acc[2][2][HNT][4];                   // [outrow][mt][nt][4] = 32
#pragma unroll
    for (int o = 0; o < 2; o++)
#pragma unroll
        for (int mt = 0; mt < 2; mt++)
#pragma unroll
            for (int j = 0; j < HNT; j++)
#pragma unroll
                for (int q = 0; q < 4; q++) acc[o][mt][j][q] = 0.f;

    for (int src = 0; src < nSrc; src++) {
        const float* ap = src ? a1 : a0;
        for (int r = y0 - 1; r <= y0 + 2; r++) {
            if (r < 0 || r >= IMG) continue;
            __syncthreads();
            // ---- fill smem with input row r (slots 0..129 = x0-1..x0+128), hi/lo ----
            const float* rowp = ap + ((size_t)b * HW + (size_t)r * IMG) * 64;
            for (int i = tid; i < 130 * 16; i += 512) {
                int slot = i >> 4, cg = (i & 15) << 2;
                int ax = x0 - 1 + slot;
                float4 f = (ax >= 0 && ax < IMG)
                         ? *(const float4*)(rowp + (size_t)ax * 64 + cg)
                         : make_float4(0.f, 0.f, 0.f, 0.f);
                __nv_bfloat16 h0 = __float2bfloat16(f.x), h1 = __float2bfloat16(f.y);
                __nv_bfloat16 h2 = __float2bfloat16(f.z), h3 = __float2bfloat16(f.w);
                *(unsigned*)&sA[0][slot][cg]     = pk(h0, h1);
                *(unsigned*)&sA[0][slot][cg + 2] = pk(h2, h3);
                *(unsigned*)&sA[1][slot][cg]     = pk(__float2bfloat16(f.x - __bfloat162float(h0)),
                                                      __float2bfloat16(f.y - __bfloat162float(h1)));
                *(unsigned*)&sA[1][slot][cg + 2] = pk(__float2bfloat16(f.z - __bfloat162float(h2)),
                                                      __float2bfloat16(f.w - __bfloat162float(h3)));
            }
            __syncthreads();
            const int ky0 = r - y0 + 1;          // tap for outrow 0
            const int ky1 = r - y0;              // tap for outrow 1
            const bool v0ok = (ky0 <= 2);
            const bool v1ok = (ky1 >= 0);
#pragma unroll
            for (int kx = 0; kx < 3; kx++) {
                const unsigned* cb0 = wfL + (size_t)(src * 9 + ky0 * 3 + kx) * 4096;
                const unsigned* cb1 = wfL + (size_t)(src * 9 + ky1 * 3 + kx) * 4096;
#pragma unroll
                for (int ks = 0; ks < 4; ks++) {
                    const int kh = ks * 16 + ((lane >> 4) << 3);
                    unsigned A[2][4];
                    // ---- stage 1: Ah ----
#pragma unroll
                    for (int mt = 0; mt < 2; mt++) {
                        int slot = mw * 32 + mt * 16 + (lane & 15) + kx;
                        LDMX4(A[mt], smem_u32(&sA[0][slot][kh]));
                    }
                    uint2 bh[2][HNT];
#pragma unroll
                    for (int o = 0; o < 2; o++) {
                        if (o == 0 ? !v0ok : !v1ok) continue;
                        const unsigned* cb = (o == 0) ? cb0 : cb1;
                        const unsigned* wh = cb + ks * 512;          // term 0
                        const unsigned* wl = cb + 2048 + ks * 512;   // term 1
#pragma unroll
                        for (int j = 0; j < HNT; j++) {
                            bh[o][j] = __ldg((const uint2*)(wh + (size_t)j * 64));
                            uint2 bl = __ldg((const uint2*)(wl + (size_t)j * 64));
#pragma unroll
                            for (int mt = 0; mt < 2; mt++) {
                                MMA_BF16(acc[o][mt][j], A[mt], bh[o][j].x, bh[o][j].y);
                                MMA_BF16(acc[o][mt][j], A[mt], bl.x, bl.y);
                            }
                        }
                    }
                    // ---- stage 2: Al (overwrite A regs) ----
#pragma unroll
                    for (int mt = 0; mt < 2; mt++) {
                        int slot = mw * 32 + mt * 16 + (lane & 15) + kx;
                        LDMX4(A[mt], smem_u32(&sA[1][slot][kh]));
                    }
#pragma unroll
                    for (int o = 0; o < 2; o++) {
                        if (o == 0 ? !v0ok : !v1ok) continue;
#pragma unroll
                        for (int j = 0; j < HNT; j++)
#pragma unroll
                            for (int mt = 0; mt < 2; mt++)
                                MMA_BF16(acc[o][mt][j], A[mt], bh[o][j].x, bh[o][j].y);
                    }
                }
            }
        }
    }

    // ---- epilogue: both output rows ----
#pragma unroll
    for (int o = 0; o < 2; o++) {
        const size_t pixB = (size_t)b * HW + (size_t)(y0 + o) * IMG + x0;
#pragma unroll
        for (int mt = 0; mt < 2; mt++) {
            int prow = mw * 32 + mt * 16 + (lane >> 2);
#pragma unroll
            for (int j = 0; j < HNT; j++) {
                int nt = nw * HNT + j;
                int cout = nt * 8 + ((lane & 3) << 1);
                float2 bb = *(const float2*)&bias[cout];
                float v0 = acc[o][mt][j][0] + bb.x, v1 = acc[o][mt][j][1] + bb.y;
                float v2 = acc[o][mt][j][2] + bb.x, v3 = acc[o][mt][j][3] + bb.y;
                if (relu) {
                    v0 = fmaxf(v0, 0.f); v1 = fmaxf(v1, 0.f);
                    v2 = fmaxf(v2, 0.f); v3 = fmaxf(v3, 0.f);
                }
                size_t i0 = (pixB + prow) * 64 + cout;
                size_t i1 = (pixB + prow + 8) * 64 + cout;
                if (r0) {
                    float2 q = *(const float2*)&r0[i0]; v0 += q.x; v1 += q.y;
                    q = *(const float2*)&r0[i1]; v2 += q.x; v3 += q.y;
                }
                if (r1) {
                    float2 q = *(const float2*)&r1[i0]; v0 += q.x; v1 += q.y;
                    q = *(const float2*)&r1[i1]; v2 += q.x; v3 += q.y;
                }
                *(float2*)&outN[i0] = make_float2(v0, v1);
                *(float2*)&outN[i1] = make_float2(v2, v3);
            }
        }
    }
}

// ======== 1-row variant (NCHW outputs: core/res), proven in R12 ========
template <int NT>
__global__ __launch_bounds__(256)
void tc_conv(const float* __restrict__ a0, const float* __restrict__ a1,
             const unsigned* __restrict__ wf, const float* __restrict__ bias,
             float* __restrict__ outC, int Cout, int relu)
{
    constexpr int HNT = (NT + 1) / 2;
    __shared__ __nv_bfloat16 sA[2][130][72];
    const int tid = threadIdx.x;
    const int lane = tid & 31, wid = tid >> 5;
    const int mw = wid & 3, nw = wid >> 2;
    const int t = blockIdx.x;
    const int b = t >> 9, rem = t & 511, y = rem >> 1, x0 = (rem & 1) << 7;
    const int nSrc = (a1 != nullptr) ? 2 : 1;

    float acc[2][HNT][4];
#pragma unroll
    for (int mt = 0; mt < 2; mt++)
#pragma unroll
        for (int j = 0; j < HNT; j++)
#pragma unroll
            for (int q = 0; q < 4; q++) acc[mt][j][q] = 0.f;

    for (int src = 0; src < nSrc; src++) {
        const float* ap = src ? a1 : a0;
        for (int ky = 0; ky < 3; ky++) {
            int yy = y + ky - 1;
            if (yy < 0 || yy >= IMG) continue;
            __syncthreads();
            const float* rowp = ap + ((size_t)b * HW + (size_t)yy * IMG) * 64;
            for (int i = tid; i < 130 * 16; i += 256) {
                int slot = i >> 4, cg = (i & 15) << 2;
                int ax = x0 - 1 + slot;
                float4 f = (ax >= 0 && ax < IMG)
                         ? *(const float4*)(rowp + (size_t)ax * 64 + cg)
                         : make_float4(0.f, 0.f, 0.f, 0.f);
                __nv_bfloat16 h0 = __float2bfloat16(f.x), h1 = __float2bfloat16(f.y);
                __nv_bfloat16 h2 = __float2bfloat16(f.z), h3 = __float2bfloat16(f.w);
                *(unsigned*)&sA[0][slot][cg]     = pk(h0, h1);
                *(unsigned*)&sA[0][slot][cg + 2] = pk(h2, h3);
                *(unsigned*)&sA[1][slot][cg]     = pk(__float2bfloat16(f.x - __bfloat162float(h0)),
                                                      __float2bfloat16(f.y - __bfloat162float(h1)));
                *(unsigned*)&sA[1][slot][cg + 2] = pk(__float2bfloat16(f.z - __bfloat162float(h2)),
                                                      __float2bfloat16(f.w - __bfloat162float(h3)));
            }
            __syncthreads();
            const int chunk0 = src * 9 + ky * 3;
#pragma unroll
            for (int kx = 0; kx < 3; kx++) {
#pragma unroll
                for (int ks = 0; ks < 4; ks++) {
                    unsigned Ah[2][4], Al[2][4];
#pragma unroll
                    for (int mt = 0; mt < 2; mt++) {
                        int slot = mw * 32 + mt * 16 + (lane & 15) + kx;
                        int kh = ks * 16 + ((lane >> 4) << 3);
                        LDMX4(Ah[mt], smem_u32(&sA[0][slot][kh]));
                        LDMX4(Al[mt], smem_u32(&sA[1][slot][kh]));
                    }
                    const int chunk = chunk0 + kx;
                    const unsigned* wh = wf + ((size_t)((chunk * 2 + 0) * 4 + ks) * NT) * 64;
                    const unsigned* wl = wf + ((size_t)((chunk * 2 + 1) * 4 + ks) * NT) * 64;
#pragma unroll
                    for (int j = 0; j < HNT; j++) {
                        int nt = nw * HNT + j;
                        if (nt >= NT) break;
                        uint2 bh = __ldg((const uint2*)(wh + (size_t)nt * 64 + lane * 2));
                        uint2 bl = __ldg((const uint2*)(wl + (size_t)nt * 64 + lane * 2));
#pragma unroll
                        for (int mt = 0; mt < 2; mt++) {
                            MMA_BF16(acc[mt][j], Ah[mt], bh.x, bh.y);
                            MMA_BF16(acc[mt][j], Ah[mt], bl.x, bl.y);
                            MMA_BF16(acc[mt][j], Al[mt], bh.x, bh.y);
                        }
                    }
                }
            }
        }
    }

    // ---- epilogue: NCHW fp32 ----
#pragma unroll
    for (int mt = 0; mt < 2; mt++) {
        int prow = mw * 32 + mt * 16 + (lane >> 2);
#pragma unroll
        for (int j = 0; j < HNT; j++) {
            int nt = nw * HNT + j;
            if (nt >= NT) break;
            int cout = nt * 8 + ((lane & 3) << 1);
#pragma unroll
            for (int q = 0; q < 4; q++) {
                int co = cout + (q & 1);
                if (co >= Cout) continue;
                int pr = prow + ((q >> 1) << 3);
                float v = acc[mt][j][q] + __ldg(&bias[co]);
                if (relu) v = fmaxf(v, 0.f);
                outC[((size_t)(b * Cout + co)) * HW + (size_t)y * IMG + x0 + pr] = v;
            }
        }
    }
}

// ================= SIMT conv (Cin=3 only), NHWC fp32 output =================
#define TWs 32
#define THs 16
#define COUT_PTs 8
template <int ACT>   // 1 relu, 2 lrelu(0.1)
__global__ __launch_bounds__(256, 4)
void conv3_simt(const float* __restrict__ in, const float* __restrict__ wgt,
                const float* __restrict__ bias, float* __restrict__ out)
{
    __shared__ float s_in[3][THs + 2][36];
    __shared__ float s_w[COUT_PTs][3][12];
    const int tx = threadIdx.x, ty = threadIdx.y;
    const int tid = ty * 16 + tx;
    const int cx = tx * 2;
    const int w0 = blockIdx.x * TWs;
    const int by = blockIdx.y;
    const int b = by >> 4;
    const int h0 = (by & 15) * THs;
    const int coBase = blockIdx.z * COUT_PTs;
    float acc[COUT_PTs * 2];
#pragma unroll
    for (int i = 0; i < COUT_PTs * 2; i++) acc[i] = 0.f;

    for (int ci = 0; ci < 3; ci++) {
        const float* ip = in + (size_t)(b * 3 + ci) * HW;
        for (int j = tid; j < (THs + 2) * (TWs + 2); j += 256) {
            int r = j / (TWs + 2), c = j - r * (TWs + 2);
            int hh = h0 - 1 + r, ww = w0 - 1 + c;
            float v = 0.f;
            if (hh >= 0 && hh < IMG && ww >= 0 && ww < IMG) v = ip[hh * IMG + ww];
            s_in[ci][r][c] = v;
        }
    }
    if (tid < COUT_PTs * 27) {
        int co = tid / 27, rem2 = tid % 27, ci = rem2 / 9, k = rem2 % 9;
        s_w[co][ci][k] = wgt[((size_t)(coBase + co) * 3 + ci) * 9 + k];
    }
    __syncthreads();

    for (int ci = 0; ci < 3; ci++) {
        float2 r0a = *(const float2*)&s_in[ci][ty + 0][cx];
        float2 r0b = *(const float2*)&s_in[ci][ty + 0][cx + 2];
        float2 r1a = *(const float2*)&s_in[ci][ty + 1][cx];
        float2 r1b = *(const float2*)&s_in[ci][ty + 1][cx + 2];
        float2 r2a = *(const float2*)&s_in[ci][ty + 2][cx];
        float2 r2b = *(const float2*)&s_in[ci][ty + 2][cx + 2];
#pragma unroll
        for (int co = 0; co < COUT_PTs; co++) {
            float4 wa = *(const float4*)&s_w[co][ci][0];
            float4 wb = *(const float4*)&s_w[co][ci][4];
            float w8 = s_w[co][ci][8];
            float s0 = acc[co * 2], s1 = acc[co * 2 + 1];
            s0 += r0a.x * wa.x;  s1 += r0a.y * wa.x;
            s0 += r0a.y * wa.y;  s1 += r0b.x * wa.y;
            s0 += r0b.x * wa.z;  s1 += r0b.y * wa.z;
            s0 += r1a.x * wa.w;  s1 += r1a.y * wa.w;
            s0 += r1a.y * wb.x;  s1 += r1b.x * wb.x;
            s0 += r1b.x * wb.y;  s1 += r1b.y * wb.y;
            s0 += r2a.x * wb.z;  s1 += r2a.y * wb.z;
            s0 += r2a.y * wb.w;  s1 += r2b.x * wb.w;
            s0 += r2b.x * w8;    s1 += r2b.y * w8;
            acc[co * 2] = s0; acc[co * 2 + 1] = s1;
        }
    }
    const int hh = h0 + ty, ww = w0 + cx;
    const size_t pix = (size_t)b * HW + (size_t)hh * IMG + ww;
#pragma unroll
    for (int co = 0; co < COUT_PTs; co++) {
        int cog = coBase + co;
        float v0 = acc[co * 2], v1 = acc[co * 2 + 1];
        float bb = __ldg(&bias[cog]);
        v0 += bb; v1 += bb;
        if (ACT == 1) { v0 = fmaxf(v0, 0.f); v1 = fmaxf(v1, 0.f); }
        else { v0 = (v0 >= 0.f) ? v0 : 0.1f * v0; v1 = (v1 >= 0.f) ? v1 : 0.1f * v1; }
        out[pix * 64 + cog] = v0;
        out[(pix + 1) * 64 + cog] = v1;
    }
}

// ================= KPN: per-pixel 5x5 kernels + residual =================
__global__ void kpn_kernel(const float* __restrict__ x, const float* __restrict__ core,
                           const float* __restrict__ res, float* __restrict__ out)
{
    int idx = blockIdx.x * blockDim.x + threadIdx.x;
    if (idx >= BATCH * 3 * HW) return;
    int w = idx & (IMG - 1);
    int h = (idx >> 8) & (IMG - 1);
    int bc = idx >> 16;
    int c = bc % 3, b = bc / 3;
    const float* xp = x + (size_t)bc * HW;
    const float* cp = core + (size_t)(b * 75 + c * 25) * HW + h * IMG + w;
    float s = 0.f;
#pragma unroll
    for (int ky = 0; ky < 5; ky++) {
        int hh = h + ky - 2;
#pragma unroll
        for (int kx = 0; kx < 5; kx++) {
            int ww = w + kx - 2;
            float xv = (hh >= 0 && hh < IMG && ww >= 0 && ww < IMG) ? xp[hh * IMG + ww] : 0.f;
            s += xv * cp[(ky * 5 + kx) * HW];
        }
    }
    out[idx] = s + res[idx];
}

// ================= host =================
extern "C" void kernel_launch(void* const* d_in, const int* in_sizes, int n_in,
                              void* d_out, int out_size)
{
    const float* x       = (const float*)d_in[0];
    const float* w_first = (const float*)d_in[1];
    const float* b_first = (const float*)d_in[2];
    const float* w_trunk = (const float*)d_in[3];
    const float* b_trunk = (const float*)d_in[4];
    const float* c1_w    = (const float*)d_in[5];
    const float* c1_b    = (const float*)d_in[6];
    const float* c2_w1   = (const float*)d_in[7];
    const float* c2_b1   = (const float*)d_in[8];
    const float* c2_w2   = (const float*)d_in[9];
    const float* c2_b2   = (const float*)d_in[10];
    const float* c3_w1   = (const float*)d_in[11];
    const float* c3_b1   = (const float*)d_in[12];
    const float* c3_w2   = (const float*)d_in[13];
    const float* c3_b2   = (const float*)d_in[14];
    const float* c3_w3   = (const float*)d_in[15];
    const float* c3_b3   = (const float*)d_in[16];
    float* out = (float*)d_out;
    (void)in_sizes; (void)n_in; (void)out_size;

    float *nhwc, *core, *res;
    unsigned* wf;
    cudaGetSymbolAddress((void**)&nhwc, g_nhwc);
    cudaGetSymbolAddress((void**)&core, g_core);
    cudaGetSymbolAddress((void**)&res,  g_res);
    cudaGetSymbolAddress((void**)&wf,   g_wfrag);
    const size_t PL = (size_t)NPIX * 64;
    float* fea = nhwc;
    float* bA  = nhwc + PL;
    float* bB  = nhwc + 2 * PL;
    float* bT  = nhwc + 3 * PL;

    // ---- merged weight prep: ONE launch ----
    prep_all<<<(WF_TOTAL + 255) / 256, 256>>>(w_trunk, c3_w2, c3_w3, c2_w1, c1_w, c2_w2, wf);

    dim3 sgrid(IMG / TWs, (IMG / THs) * BATCH, 8);
    dim3 sblk(16, 16);

    // 1) fea1 = lrelu(conv_first(x))
    conv3_simt<2><<<sgrid, sblk>>>(x, w_first, b_first, fea);

    // 2) 16 residual blocks on tensor cores (2-row, 512-thread kernel)
    float* cur = fea;
    for (int i = 0; i < 16; i++) {
        float* dst = (i & 1) ? bB : bA;
        const float* extra = (i == 15) ? fea : nullptr;
        tc_conv2<<<1024, 512>>>(cur, nullptr, wf + WF_TRUNK(2 * i), b_trunk + (size_t)(2 * i) * 64,
                                bT, nullptr, nullptr, 1);
        tc_conv2<<<1024, 512>>>(bT, nullptr, wf + WF_TRUNK(2 * i + 1), b_trunk + (size_t)(2 * i + 1) * 64,
                                dst, cur, extra, 0);
        cur = dst;
    }
    // cur = bB (i=15). free: bA, bT.

    // 3) image branch: t1 (SIMT) -> t2 -> t3
    conv3_simt<1><<<sgrid, sblk>>>(x, c3_w1, c3_b1, bT);
    tc_conv2<<<1024, 512>>>(bT, nullptr, wf + WF_C3W2, c3_b2, bA, nullptr, nullptr, 1);
    tc_conv2<<<1024, 512>>>(bA, nullptr, wf + WF_C3W3, c3_b3, bT, nullptr, nullptr, 0); // t3=bT

    // 4) R1 = relu(conv(concat[t3,F], c2_w1)) -> bA ; res = conv(R1, c2_w2) (NCHW)
    tc_conv2<<<1024, 512>>>(bT, cur, wf + WF_C2W1, c2_b1, bA, nullptr, nullptr, 1);
    tc_conv<1><<<2048, 256>>>(bA, nullptr, wf + WF_C2W2, c2_b2, res, 3, 0);

    // 5) core = conv(concat[t3,F], c1_w) (NCHW)
    tc_conv<10><<<2048, 256>>>(bT, cur, wf + WF_C1, c1_b, core, 75, 0);

    // 6) KPN + residual
    kpn_kernel<<<(BATCH * 3 * HW + 255) / 256, 256>>>(x, core, res, out);
}

// round 17
// speedup vs baseline: 1.9203x; 1.9203x over previous
#include <cuda_runtime.h>
#include <cuda_bf16.h>
#include <cstdint>

// ================= problem constants =================
#define IMG 256
#define BATCH 4
#define HW 65536
#define NPIX 262144          // BATCH*HW

// ================= device scratch (no allocs) =================
// NHWC fp32 planes: 0=fea1 1=bufA 2=bufB 3=bufT
__device__ __align__(16) float g_nhwc[4][(size_t)NPIX * 64];
__device__ float g_core[(size_t)BATCH * 75 * HW];
__device__ float g_res [(size_t)BATCH * 3  * HW];
// fragment-ordered bf16 weights (u32 elements), hi/lo interleaved per lane
#define WF_TRUNK(j) ((size_t)(j) * 36864)
#define WF_C3W2  1179648
#define WF_C3W3  1216512
#define WF_C2W1  1253376
#define WF_C1    1327104
#define WF_C2W2  1419264
#define WF_TOTAL 1423872
__device__ __align__(16) unsigned g_wfrag[WF_TOTAL];

// ================= helpers =================
__device__ __forceinline__ unsigned smem_u32(const void* p) {
    unsigned a;
    asm("{ .reg .u64 t; cvta.to.shared.u64 t, %1; cvt.u32.u64 %0, t; }" : "=r"(a) : "l"(p));
    return a;
}
__device__ __forceinline__ unsigned pk(__nv_bfloat16 a, __nv_bfloat16 b) {
    return (unsigned)__bfloat16_as_ushort(a) | ((unsigned)__bfloat16_as_ushort(b) << 16);
}
#define MMA_BF16(acc, a, b0, b1)                                              \
    asm volatile(                                                             \
        "mma.sync.aligned.m16n8k16.row.col.f32.bf16.bf16.f32 "               \
        "{%0,%1,%2,%3}, {%4,%5,%6,%7}, {%8,%9}, {%0,%1,%2,%3};"              \
        : "+f"((acc)[0]), "+f"((acc)[1]), "+f"((acc)[2]), "+f"((acc)[3])      \
        : "r"((a)[0]), "r"((a)[1]), "r"((a)[2]), "r"((a)[3]),                 \
          "r"(b0), "r"(b1))
#define LDMX4(dst, addr)                                                      \
    asm volatile("ldmatrix.sync.aligned.m8n8.x4.shared.b16 {%0,%1,%2,%3}, [%4];" \
                 : "=r"((dst)[0]), "=r"((dst)[1]), "=r"((dst)[2]), "=r"((dst)[3]) \
                 : "r"(addr))

// ================= merged weight prep: all layers in ONE launch =================
// NEW layout: u32 index = (((chunk*4 + kstep)*NT + ntile)*32 + lane)*4 + comp,
//   comp = term*2 + r. value: halves {B[k][n], B[k+1][n]},
//   n = ntile*8 + lane/4, k = kstep*16 + (lane%4)*2 + 8r, ci = src*64 + k.
// One uint4 per lane = {bh.x, bh.y, bl.x, bl.y}.
__device__ __forceinline__ void prep_one(const float* __restrict__ w, unsigned* __restrict__ dst,
                                         int idx, int Cout, int CinW, int NT)
{
    int comp = idx & 3;
    int lane = (idx >> 2) & 31;
    int term = comp >> 1, r = comp & 1;
    int tmp = idx >> 7;
    int ntile = tmp % NT; tmp /= NT;
    int kstep = tmp & 3;
    int chunk = tmp >> 2;
    int src = chunk / 9, t9 = chunk % 9, ky = t9 / 3, kx = t9 % 3;
    int n = ntile * 8 + (lane >> 2);
    int k = kstep * 16 + ((lane & 3) << 1) + 8 * r;
    int ci = src * 64 + k;
    float v0 = 0.f, v1 = 0.f;
    if (n < Cout) {
        if (ci < CinW)     v0 = w[(((size_t)n * CinW + ci) * 3 + ky) * 3 + kx];
        if (ci + 1 < CinW) v1 = w[(((size_t)n * CinW + ci + 1) * 3 + ky) * 3 + kx];
    }
    __nv_bfloat16 h0 = __float2bfloat16(v0), h1 = __float2bfloat16(v1);
    unsigned outv;
    if (term == 0) outv = pk(h0, h1);
    else outv = pk(__float2bfloat16(v0 - __bfloat162float(h0)),
                   __float2bfloat16(v1 - __bfloat162float(h1)));
    dst[idx] = outv;
}

__global__ void prep_all(const float* __restrict__ w_trunk,
                         const float* __restrict__ c3_w2, const float* __restrict__ c3_w3,
                         const float* __restrict__ c2_w1, const float* __restrict__ c1_w,
                         const float* __restrict__ c2_w2, unsigned* __restrict__ wf)
{
    int g = blockIdx.x * 256 + threadIdx.x;
    if (g >= WF_TOTAL) return;
    if (g < WF_C3W2) {
        int j = g / 36864;
        prep_one(w_trunk + (size_t)j * 36864, wf + WF_TRUNK(j), g % 36864, 64, 64, 8);
    } else if (g < WF_C3W3) {
        prep_one(c3_w2, wf + WF_C3W2, g - WF_C3W2, 64, 64, 8);
    } else if (g < WF_C2W1) {
        prep_one(c3_w3, wf + WF_C3W3, g - WF_C3W3, 64, 64, 8);
    } else if (g < WF_C1) {
        prep_one(c2_w1, wf + WF_C2W1, g - WF_C2W1, 64, 128, 8);
    } else if (g < WF_C2W2) {
        prep_one(c1_w, wf + WF_C1, g - WF_C1, 75, 128, 10);
    } else {
        prep_one(c2_w2, wf + WF_C2W2, g - WF_C2W2, 3, 64, 1);
    }
}

// ======== 2-row tensor-core implicit-GEMM 3x3 conv (mma.sync bf16, 3-term) ========
// CTA: 256 threads, 8 warps = 4 M x 2 N. 2 output rows x 128 pixels x 64 couts.
// B fragments: ONE uint4 load per (o, nt) carries hi+lo terms.
__global__ __launch_bounds__(256, 2)
void tc_conv2(const float* __restrict__ a0, const float* __restrict__ a1,
              const unsigned* __restrict__ wf, const float* __restrict__ bias,
              float* __restrict__ outN,
              const float* __restrict__ r0, const float* __restrict__ r1, int relu)
{
    constexpr int NT = 8, HNT = 4;
    __shared__ __nv_bfloat16 sA[2][130][72];   // [hi/lo][slot][ci] stride 144B
    const int tid = threadIdx.x;
    const int lane = tid & 31, wid = tid >> 5;
    const int mw = wid & 3, nw = wid >> 2;
    const int t = blockIdx.x;
    const int b = t >> 8, rem = t & 255;
    const int y0 = (rem >> 1) << 1, x0 = (rem & 1) << 7;
    const int nSrc = (a1 != nullptr) ? 2 : 1;
    // invariant per-thread B base: + nt0*128 + lane*4
    const unsigned* wfL = wf + (size_t)(nw * HNT) * 128 + lane * 4;

    float acc[2][2][HNT][4];                   // [outrow][mt][nt][4]
#pragma unroll
    for (int o = 0; o < 2; o++)
#pragma unroll
        for (int mt = 0; mt < 2; mt++)
#pragma unroll
            for (int j = 0; j < HNT; j++)
#pragma unroll
                for (int q = 0; q < 4; q++) acc[o][mt][j][q] = 0.f;

    for (int src = 0; src < nSrc; src++) {
        const float* ap = src ? a1 : a0;
        for (int r = y0 - 1; r <= y0 + 2; r++) {
            if (r < 0 || r >= IMG) continue;
            __syncthreads();
            // ---- fill smem with input row r (slots 0..129 = x0-1..x0+128), hi/lo ----
            const float* rowp = ap + ((size_t)b * HW + (size_t)r * IMG) * 64;
            for (int i = tid; i < 130 * 16; i += 256) {
                int slot = i >> 4, cg = (i & 15) << 2;
                int ax = x0 - 1 + slot;
                float4 f = (ax >= 0 && ax < IMG)
                         ? *(const float4*)(rowp + (size_t)ax * 64 + cg)
                         : make_float4(0.f, 0.f, 0.f, 0.f);
                __nv_bfloat16 h0 = __float2bfloat16(f.x), h1 = __float2bfloat16(f.y);
                __nv_bfloat16 h2 = __float2bfloat16(f.z), h3 = __float2bfloat16(f.w);
                *(unsigned*)&sA[0][slot][cg]     = pk(h0, h1);
                *(unsigned*)&sA[0][slot][cg + 2] = pk(h2, h3);
                *(unsigned*)&sA[1][slot][cg]     = pk(__float2bfloat16(f.x - __bfloat162float(h0)),
                                                      __float2bfloat16(f.y - __bfloat162float(h1)));
                *(unsigned*)&sA[1][slot][cg + 2] = pk(__float2bfloat16(f.z - __bfloat162float(h2)),
                                                      __float2bfloat16(f.w - __bfloat162float(h3)));
            }
            __syncthreads();
            const int ky0 = r - y0 + 1;          // tap for outrow 0
            const int ky1 = r - y0;              // tap for outrow 1
            const bool v0ok = (ky0 <= 2);
            const bool v1ok = (ky1 >= 0);
#pragma unroll
            for (int kx = 0; kx < 3; kx++) {
                // chunk stride (u32): 4*NT*128 = 4096
                const unsigned* cb0 = wfL + (size_t)(src * 9 + ky0 * 3 + kx) * 4096;
                const unsigned* cb1 = wfL + (size_t)(src * 9 + ky1 * 3 + kx) * 4096;
#pragma unroll
                for (int ks = 0; ks < 4; ks++) {
                    // ---- A fragments: hi and lo planes, both m-tiles ----
                    unsigned Ah[2][4], Al[2][4];
#pragma unroll
                    for (int mt = 0; mt < 2; mt++) {
                        int slot = mw * 32 + mt * 16 + (lane & 15) + kx;
                        int kh = ks * 16 + ((lane >> 4) << 3);
                        LDMX4(Ah[mt], smem_u32(&sA[0][slot][kh]));
                        LDMX4(Al[mt], smem_u32(&sA[1][slot][kh]));
                    }
                    // ---- MMA blocks per valid output row, B = one uint4/nt ----
#pragma unroll
                    for (int o = 0; o < 2; o++) {
                        if (o == 0 ? !v0ok : !v1ok) continue;
                        const unsigned* cb = (o == 0) ? cb0 : cb1;
                        uint4 B[HNT];
#pragma unroll
                        for (int j = 0; j < HNT; j++)
                            B[j] = __ldg((const uint4*)(cb + ks * 1024 + (size_t)j * 128));
#pragma unroll
                        for (int j = 0; j < HNT; j++) {
#pragma unroll
                            for (int mt = 0; mt < 2; mt++) {
                                MMA_BF16(acc[o][mt][j], Ah[mt], B[j].x, B[j].y);
                                MMA_BF16(acc[o][mt][j], Ah[mt], B[j].z, B[j].w);
                                MMA_BF16(acc[o][mt][j], Al[mt], B[j].x, B[j].y);
                            }
                        }
                    }
                }
            }
        }
    }

    // ---- epilogue: both output rows ----
#pragma unroll
    for (int o = 0; o < 2; o++) {
        const size_t pixB = (size_t)b * HW + (size_t)(y0 + o) * IMG + x0;
#pragma unroll
        for (int mt = 0; mt < 2; mt++) {
            int prow = mw * 32 + mt * 16 + (lane >> 2);
#pragma unroll
            for (int j = 0; j < HNT; j++) {
                int nt = nw * HNT + j;
                int cout = nt * 8 + ((lane & 3) << 1);
                float2 bb = *(const float2*)&bias[cout];
                float v0 = acc[o][mt][j][0] + bb.x, v1 = acc[o][mt][j][1] + bb.y;
                float v2 = acc[o][mt][j][2] + bb.x, v3 = acc[o][mt][j][3] + bb.y;
                if (relu) {
                    v0 = fmaxf(v0, 0.f); v1 = fmaxf(v1, 0.f);
                    v2 = fmaxf(v2, 0.f); v3 = fmaxf(v3, 0.f);
                }
                size_t i0 = (pixB + prow) * 64 + cout;
                size_t i1 = (pixB + prow + 8) * 64 + cout;
                if (r0) {
                    float2 q = *(const float2*)&r0[i0]; v0 += q.x; v1 += q.y;
                    q = *(const float2*)&r0[i1]; v2 += q.x; v3 += q.y;
                }
                if (r1) {
                    float2 q = *(const float2*)&r1[i0]; v0 += q.x; v1 += q.y;
                    q = *(const float2*)&r1[i1]; v2 += q.x; v3 += q.y;
                }
                *(float2*)&outN[i0] = make_float2(v0, v1);
                *(float2*)&outN[i1] = make_float2(v2, v3);
            }
        }
    }
}

// ======== 1-row variant (NCHW outputs: core/res) ========
template <int NT>
__global__ __launch_bounds__(256)
void tc_conv(const float* __restrict__ a0, const float* __restrict__ a1,
             const unsigned* __restrict__ wf, const float* __restrict__ bias,
             float* __restrict__ outC, int Cout, int relu)
{
    constexpr int HNT = (NT + 1) / 2;
    __shared__ __nv_bfloat16 sA[2][130][72];
    const int tid = threadIdx.x;
    const int lane = tid & 31, wid = tid >> 5;
    const int mw = wid & 3, nw = wid >> 2;
    const int t = blockIdx.x;
    const int b = t >> 9, rem = t & 511, y = rem >> 1, x0 = (rem & 1) << 7;
    const int nSrc = (a1 != nullptr) ? 2 : 1;

    float acc[2][HNT][4];
#pragma unroll
    for (int mt = 0; mt < 2; mt++)
#pragma unroll
        for (int j = 0; j < HNT; j++)
#pragma unroll
            for (int q = 0; q < 4; q++) acc[mt][j][q] = 0.f;

    for (int src = 0; src < nSrc; src++) {
        const float* ap = src ? a1 : a0;
        for (int ky = 0; ky < 3; ky++) {
            int yy = y + ky - 1;
            if (yy < 0 || yy >= IMG) continue;
            __syncthreads();
            const float* rowp = ap + ((size_t)b * HW + (size_t)yy * IMG) * 64;
            for (int i = tid; i < 130 * 16; i += 256) {
                int slot = i >> 4, cg = (i & 15) << 2;
                int ax = x0 - 1 + slot;
                float4 f = (ax >= 0 && ax < IMG)
                         ? *(const float4*)(rowp + (size_t)ax * 64 + cg)
                         : make_float4(0.f, 0.f, 0.f, 0.f);
                __nv_bfloat16 h0 = __float2bfloat16(f.x), h1 = __float2bfloat16(f.y);
                __nv_bfloat16 h2 = __float2bfloat16(f.z), h3 = __float2bfloat16(f.w);
                *(unsigned*)&sA[0][slot][cg]     = pk(h0, h1);
                *(unsigned*)&sA[0][slot][cg + 2] = pk(h2, h3);
                *(unsigned*)&sA[1][slot][cg]     = pk(__float2bfloat16(f.x - __bfloat162float(h0)),
                                                      __float2bfloat16(f.y - __bfloat162float(h1)));
                *(unsigned*)&sA[1][slot][cg + 2] = pk(__float2bfloat16(f.z - __bfloat162float(h2)),
                                                      __float2bfloat16(f.w - __bfloat162float(h3)));
            }
            __syncthreads();
            const int chunk0 = src * 9 + ky * 3;
#pragma unroll
            for (int kx = 0; kx < 3; kx++) {
#pragma unroll
                for (int ks = 0; ks < 4; ks++) {
                    unsigned Ah[2][4], Al[2][4];
#pragma unroll
                    for (int mt = 0; mt < 2; mt++) {
                        int slot = mw * 32 + mt * 16 + (lane & 15) + kx;
                        int kh = ks * 16 + ((lane >> 4) << 3);
                        LDMX4(Ah[mt], smem_u32(&sA[0][slot][kh]));
                        LDMX4(Al[mt], smem_u32(&sA[1][slot][kh]));
                    }
                    const int chunk = chunk0 + kx;
                    // base: ((chunk*4 + ks)*NT + nt)*128 + lane*4
                    const unsigned* cb = wf + (size_t)(chunk * 4 + ks) * NT * 128 + lane * 4;
#pragma unroll
                    for (int j = 0; j < HNT; j++) {
                        int nt = nw * HNT + j;
                        if (nt >= NT) break;
                        uint4 B = __ldg((const uint4*)(cb + (size_t)nt * 128));
#pragma unroll
                        for (int mt = 0; mt < 2; mt++) {
                            MMA_BF16(acc[mt][j], Ah[mt], B.x, B.y);
                            MMA_BF16(acc[mt][j], Ah[mt], B.z, B.w);
                            MMA_BF16(acc[mt][j], Al[mt], B.x, B.y);
                        }
                    }
                }
            }
        }
    }

    // ---- epilogue: NCHW fp32 ----
#pragma unroll
    for (int mt = 0; mt < 2; mt++) {
        int prow = mw * 32 + mt * 16 + (lane >> 2);
#pragma unroll
        for (int j = 0; j < HNT; j++) {
            int nt = nw * HNT + j;
            if (nt >= NT) break;
            int cout = nt * 8 + ((lane & 3) << 1);
#pragma unroll
            for (int q = 0; q < 4; q++) {
                int co = cout + (q & 1);
                if (co >= Cout) continue;
                int pr = prow + ((q >> 1) << 3);
                float v = acc[mt][j][q] + __ldg(&bias[co]);
                if (relu) v = fmaxf(v, 0.f);
                outC[((size_t)(b * Cout + co)) * HW + (size_t)y * IMG + x0 + pr] = v;
            }
        }
    }
}

// ================= SIMT conv (Cin=3 only), NHWC fp32 output =================
#define TWs 32
#define THs 16
#define COUT_PTs 8
template <int ACT>   // 1 relu, 2 lrelu(0.1)
__global__ __launch_bounds__(256, 4)
void conv3_simt(const float* __restrict__ in, const float* __restrict__ wgt,
                const float* __restrict__ bias, float* __restrict__ out)
{
    __shared__ float s_in[3][THs + 2][36];
    __shared__ float s_w[COUT_PTs][3][12];
    const int tx = threadIdx.x, ty = threadIdx.y;
    const int tid = ty * 16 + tx;
    const int cx = tx * 2;
    const int w0 = blockIdx.x * TWs;
    const int by = blockIdx.y;
    const int b = by >> 4;
    const int h0 = (by & 15) * THs;
    const int coBase = blockIdx.z * COUT_PTs;
    float acc[COUT_PTs * 2];
#pragma unroll
    for (int i = 0; i < COUT_PTs * 2; i++) acc[i] = 0.f;

    for (int ci = 0; ci < 3; ci++) {
        const float* ip = in + (size_t)(b * 3 + ci) * HW;
        for (int j = tid; j < (THs + 2) * (TWs + 2); j += 256) {
            int r = j / (TWs + 2), c = j - r * (TWs + 2);
            int hh = h0 - 1 + r, ww = w0 - 1 + c;
            float v = 0.f;
            if (hh >= 0 && hh < IMG && ww >= 0 && ww < IMG) v = ip[hh * IMG + ww];
            s_in[ci][r][c] = v;
        }
    }
    if (tid < COUT_PTs * 27) {
        int co = tid / 27, rem2 = tid % 27, ci = rem2 / 9, k = rem2 % 9;
        s_w[co][ci][k] = wgt[((size_t)(coBase + co) * 3 + ci) * 9 + k];
    }
    __syncthreads();

    for (int ci = 0; ci < 3; ci++) {
        float2 r0a = *(const float2*)&s_in[ci][ty + 0][cx];
        float2 r0b = *(const float2*)&s_in[ci][ty + 0][cx + 2];
        float2 r1a = *(const float2*)&s_in[ci][ty + 1][cx];
        float2 r1b = *(const float2*)&s_in[ci][ty + 1][cx + 2];
        float2 r2a = *(const float2*)&s_in[ci][ty + 2][cx];
        float2 r2b = *(const float2*)&s_in[ci][ty + 2][cx + 2];
#pragma unroll
        for (int co = 0; co < COUT_PTs; co++) {
            float4 wa = *(const float4*)&s_w[co][ci][0];
            float4 wb = *(const float4*)&s_w[co][ci][4];
            float w8 = s_w[co][ci][8];
            float s0 = acc[co * 2], s1 = acc[co * 2 + 1];
            s0 += r0a.x * wa.x;  s1 += r0a.y * wa.x;
            s0 += r0a.y * wa.y;  s1 += r0b.x * wa.y;
            s0 += r0b.x * wa.z;  s1 += r0b.y * wa.z;
            s0 += r1a.x * wa.w;  s1 += r1a.y * wa.w;
            s0 += r1a.y * wb.x;  s1 += r1b.x * wb.x;
            s0 += r1b.x * wb.y;  s1 += r1b.y * wb.y;
            s0 += r2a.x * wb.z;  s1 += r2a.y * wb.z;
            s0 += r2a.y * wb.w;  s1 += r2b.x * wb.w;
            s0 += r2b.x * w8;    s1 += r2b.y * w8;
            acc[co * 2] = s0; acc[co * 2 + 1] = s1;
        }
    }
    const int hh = h0 + ty, ww = w0 + cx;
    const size_t pix = (size_t)b * HW + (size_t)hh * IMG + ww;
#pragma unroll
    for (int co = 0; co < COUT_PTs; co++) {
        int cog = coBase + co;
        float v0 = acc[co * 2], v1 = acc[co * 2 + 1];
        float bb = __ldg(&bias[cog]);
        v0 += bb; v1 += bb;
        if (ACT == 1) { v0 = fmaxf(v0, 0.f); v1 = fmaxf(v1, 0.f); }
        else { v0 = (v0 >= 0.f) ? v0 : 0.1f * v0; v1 = (v1 >= 0.f) ? v1 : 0.1f * v1; }
        out[pix * 64 + cog] = v0;
        out[(pix + 1) * 64 + cog] = v1;
    }
}

// ================= KPN: per-pixel 5x5 kernels + residual =================
__global__ void kpn_kernel(const float* __restrict__ x, const float* __restrict__ core,
                           const float* __restrict__ res, float* __restrict__ out)
{
    int idx = blockIdx.x * blockDim.x + threadIdx.x;
    if (idx >= BATCH * 3 * HW) return;
    int w = idx & (IMG - 1);
    int h = (idx >> 8) & (IMG - 1);
    int bc = idx >> 16;
    int c = bc % 3, b = bc / 3;
    const float* xp = x + (size_t)bc * HW;
    const float* cp = core + (size_t)(b * 75 + c * 25) * HW + h * IMG + w;
    float s = 0.f;
#pragma unroll
    for (int ky = 0; ky < 5; ky++) {
        int hh = h + ky - 2;
#pragma unroll
        for (int kx = 0; kx < 5; kx++) {
            int ww = w + kx - 2;
            float xv = (hh >= 0 && hh < IMG && ww >= 0 && ww < IMG) ? xp[hh * IMG + ww] : 0.f;
            s += xv * cp[(ky * 5 + kx) * HW];
        }
    }
    out[idx] = s + res[idx];
}

// ================= host =================
extern "C" void kernel_launch(void* const* d_in, const int* in_sizes, int n_in,
                              void* d_out, int out_size)
{
    const float* x       = (const float*)d_in[0];
    const float* w_first = (const float*)d_in[1];
    const float* b_first = (const float*)d_in[2];
    const float* w_trunk = (const float*)d_in[3];
    const float* b_trunk = (const float*)d_in[4];
    const float* c1_w    = (const float*)d_in[5];
    const float* c1_b    = (const float*)d_in[6];
    const float* c2_w1   = (const float*)d_in[7];
    const float* c2_b1   = (const float*)d_in[8];
    const float* c2_w2   = (const float*)d_in[9];
    const float* c2_b2   = (const float*)d_in[10];
    const float* c3_w1   = (const float*)d_in[11];
    const float* c3_b1   = (const float*)d_in[12];
    const float* c3_w2   = (const float*)d_in[13];
    const float* c3_b2   = (const float*)d_in[14];
    const float* c3_w3   = (const float*)d_in[15];
    const float* c3_b3   = (const float*)d_in[16];
    float* out = (float*)d_out;
    (void)in_sizes; (void)n_in; (void)out_size;

    float *nhwc, *core, *res;
    unsigned* wf;
    cudaGetSymbolAddress((void**)&nhwc, g_nhwc);
    cudaGetSymbolAddress((void**)&core, g_core);
    cudaGetSymbolAddress((void**)&res,  g_res);
    cudaGetSymbolAddress((void**)&wf,   g_wfrag);
    const size_t PL = (size_t)NPIX * 64;
    float* fea = nhwc;
    float* bA  = nhwc + PL;
    float* bB  = nhwc + 2 * PL;
    float* bT  = nhwc + 3 * PL;

    // ---- merged weight prep: ONE launch ----
    prep_all<<<(WF_TOTAL + 255) / 256, 256>>>(w_trunk, c3_w2, c3_w3, c2_w1, c1_w, c2_w2, wf);

    dim3 sgrid(IMG / TWs, (IMG / THs) * BATCH, 8);
    dim3 sblk(16, 16);

    // 1) fea1 = lrelu(conv_first(x))
    conv3_simt<2><<<sgrid, sblk>>>(x, w_first, b_first, fea);

    // 2) 16 residual blocks on tensor cores (2-row kernel)
    float* cur = fea;
    for (int i = 0; i < 16; i++) {
        float* dst = (i & 1) ? bB : bA;
        const float* extra = (i == 15) ? fea : nullptr;
        tc_conv2<<<1024, 256>>>(cur, nullptr, wf + WF_TRUNK(2 * i), b_trunk + (size_t)(2 * i) * 64,
                                bT, nullptr, nullptr, 1);
        tc_conv2<<<1024, 256>>>(bT, nullptr, wf + WF_TRUNK(2 * i + 1), b_trunk + (size_t)(2 * i + 1) * 64,
                                dst, cur, extra, 0);
        cur = dst;
    }
    // cur = bB (i=15). free: bA, bT.

    // 3) image branch: t1 (SIMT) -> t2 -> t3
    conv3_simt<1><<<sgrid, sblk>>>(x, c3_w1, c3_b1, bT);
    tc_conv2<<<1024, 256>>>(bT, nullptr, wf + WF_C3W2, c3_b2, bA, nullptr, nullptr, 1);
    tc_conv2<<<1024, 256>>>(bA, nullptr, wf + WF_C3W3, c3_b3, bT, nullptr, nullptr, 0); // t3=bT

    // 4) R1 = relu(conv(concat[t3,F], c2_w1)) -> bA ; res = conv(R1, c2_w2) (NCHW)
    tc_conv2<<<1024, 256>>>(bT, cur, wf + WF_C2W1, c2_b1, bA, nullptr, nullptr, 1);
    tc_conv<1><<<2048, 256>>>(bA, nullptr, wf + WF_C2W2, c2_b2, res, 3, 0);

    // 5) core = conv(concat[t3,F], c1_w) (NCHW)
    tc_conv<10><<<2048, 256>>>(bT, cur, wf + WF_C1, c1_b, core, 75, 0);

    // 6) KPN + residual
    kpn_kernel<<<(BATCH * 3 * HW + 255) / 256, 256>>>(x, core, res, out);
}